// round 7
// baseline (speedup 1.0000x reference)
#include <cuda_runtime.h>
#include <cuda_bf16.h>
#include <cstdint>

#define N_NODES   100000
#define D_FEAT    128
#define HID       64
#define N_SAMPLES 250000

// Merged per-node table (51.2 MB scratch).
// T[n][ 0: 64] = x1[n]@w1[0:128]   + x2[n]@w1[256:384] + b1   (src half)
// T[n][64:128] = x1[n]@w1[128:256] + x2[n]@w1[384:512]        (dst half)
__device__ float g_T[(size_t)N_NODES * 128];

// Pre-split B operand, chunk-major: [chunk c][n 0..127][kk 0..63] bf16.
__device__ __nv_bfloat16 g_Bhi[4 * 128 * 64];
__device__ __nv_bfloat16 g_Blo[4 * 128 * 64];

__device__ int g_idx_is64;   // 1 if train_sample is int64, 0 if int32

// ---------------- helpers ----------------
__device__ __forceinline__ uint32_t smem_u32(const void* p) {
    uint32_t a;
    asm("{ .reg .u64 t; cvta.to.shared.u64 t, %1; cvt.u32.u64 %0, t; }"
        : "=r"(a) : "l"(p));
    return a;
}
__device__ __forceinline__ void cp_async16(uint32_t dst, const void* src) {
    asm volatile("cp.async.cg.shared.global [%0], [%1], 16;"
                 :: "r"(dst), "l"(src) : "memory");
}
__device__ __forceinline__ void cp_commit() {
    asm volatile("cp.async.commit_group;" ::: "memory");
}
__device__ __forceinline__ void cp_wait0() {
    asm volatile("cp.async.wait_group 0;" ::: "memory");
}
__device__ __forceinline__ void ldmatrix_x4(uint32_t& r0, uint32_t& r1,
                                            uint32_t& r2, uint32_t& r3,
                                            uint32_t addr) {
    asm volatile("ldmatrix.sync.aligned.m8n8.x4.shared.b16 {%0,%1,%2,%3}, [%4];"
                 : "=r"(r0), "=r"(r1), "=r"(r2), "=r"(r3) : "r"(addr));
}
__device__ __forceinline__ void mma_bf16(float& d0, float& d1, float& d2, float& d3,
                                         uint32_t a0, uint32_t a1, uint32_t a2, uint32_t a3,
                                         uint32_t b0, uint32_t b1) {
    asm volatile(
        "mma.sync.aligned.m16n8k16.row.col.f32.bf16.bf16.f32 "
        "{%0,%1,%2,%3}, {%4,%5,%6,%7}, {%8,%9}, {%0,%1,%2,%3};"
        : "+f"(d0), "+f"(d1), "+f"(d2), "+f"(d3)
        : "r"(a0), "r"(a1), "r"(a2), "r"(a3), "r"(b0), "r"(b1));
}

// ============================================================================
// Kernel 0: dtype detect (block 0) + B split (32 blocks).
// ============================================================================
__global__ void prep_kernel(const unsigned int* __restrict__ ts32,
                            const float* __restrict__ w1)
{
    int t = threadIdx.x;

    if (blockIdx.x == 0) {
        __shared__ int nonzero;
        if (t == 0) nonzero = 0;
        __syncthreads();
        unsigned int acc = 0;
#pragma unroll
        for (int i = 0; i < 16; i++) acc |= ts32[2 * (t + 256 * i) + 1];
        if (acc) atomicOr(&nonzero, 1);
        __syncthreads();
        if (t == 0) g_idx_is64 = nonzero ? 0 : 1;
    }

#pragma unroll
    for (int i = 0; i < 4; i++) {
        int idx = blockIdx.x * 1024 + i * 256 + t;     // 0..32767
        int c  = idx >> 13;
        int n  = (idx >> 6) & 127;
        int kk = idx & 63;
        int gk = c * 64 + kk;
        int wrow = (n < 64) ? ((gk < 128) ? gk : gk + 128)
                            : ((gk < 128) ? gk + 128 : gk + 256);
        int wcol = n & 63;
        float v = w1[wrow * HID + wcol];
        __nv_bfloat16 h = __float2bfloat16_rn(v);
        __nv_bfloat16 l = __float2bfloat16_rn(v - __bfloat162float(h));
        g_Bhi[idx] = h;
        g_Blo[idx] = l;
    }
}

// ============================================================================
// Kernel 1: warp-MMA precompute GEMM (bf16 hi/lo split, fp32 accumulate).
// CTA: 512 threads (16 warps, 4/SMSP), 128M x 128N, K=256 in four 64-chunks.
// Warp tile 32x32 (2x4 m16n8 tiles).
// A path: cp.async fp32 chunk into double-buffered smem stage (zero register
// cost, overlaps MMA), then in-smem convert to bf16 hi/lo (single padded
// buffer, ldmatrix-fed). B frags direct from pre-split global (L1-resident).
// ============================================================================
#define A_STRIDE  72                      // bf16/row: 64 data + 8 pad (144 B)
#define F32_STAGE 32768                   // 128 rows x 64 f32
#define BF_OFF    (2 * F32_STAGE)         // 65536
#define AHALF     (128 * A_STRIDE * 2)    // 18432 B (one of Ahi/Alo)
#define SMEM_TOT  (BF_OFF + 2 * AHALF)    // 102400 B

__global__ __launch_bounds__(512, 1)
void precompute_mma_kernel(const float* __restrict__ in1,
                           const float* __restrict__ in2,
                           const float* __restrict__ b1)
{
    extern __shared__ char smem[];
    const uint32_t sbase = smem_u32(smem);

    const int t      = threadIdx.x;
    const int wid    = t >> 5;
    const int lane   = t & 31;
    const int warp_m = wid >> 2;         // 0..3  (32-row strips)
    const int warp_n = wid & 3;          // 0..3  (32-col strips)
    const int row0   = blockIdx.x * 128;

    float acc[2][4][4];
#pragma unroll
    for (int mt = 0; mt < 2; mt++)
#pragma unroll
        for (int nt = 0; nt < 4; nt++)
#pragma unroll
            for (int r = 0; r < 4; r++) acc[mt][nt][r] = 0.f;

    const int lm_row  = lane & 15;
    const int lm_koff = (lane >> 4) * 16;

    // Per-thread copy/convert slots: linear = t + 512*i, i<4.
    // r = linear>>4 (row 0..127), c4 = linear&15 (float4 slot along k).
    auto issue_cp = [&](int c, int s) {
        const float* __restrict__ in = (c < 2) ? in1 : in2;
        const int col0 = (c & 1) * 64;
#pragma unroll
        for (int i = 0; i < 4; i++) {
            int linear = t + 512 * i;
            int r  = linear >> 4;
            int c4 = linear & 15;
            int grow = row0 + r;
            if (grow >= N_NODES) grow = 0;   // rows OOB feed unstored outputs
            cp_async16(sbase + s * F32_STAGE + linear * 16,
                       &in[(size_t)grow * D_FEAT + col0 + 4 * c4]);
        }
        cp_commit();
    };
    auto convert = [&](int s) {
        __nv_bfloat16* Ahi = (__nv_bfloat16*)(smem + BF_OFF);
        __nv_bfloat16* Alo = (__nv_bfloat16*)(smem + BF_OFF + AHALF);
#pragma unroll
        for (int i = 0; i < 4; i++) {
            int linear = t + 512 * i;
            int r  = linear >> 4;
            int c4 = linear & 15;
            float4 v = *(const float4*)(smem + s * F32_STAGE + linear * 16);
            __nv_bfloat16 h0 = __float2bfloat16_rn(v.x), h1 = __float2bfloat16_rn(v.y);
            __nv_bfloat16 h2 = __float2bfloat16_rn(v.z), h3 = __float2bfloat16_rn(v.w);
            __nv_bfloat16 l0 = __float2bfloat16_rn(v.x - __bfloat162float(h0));
            __nv_bfloat16 l1 = __float2bfloat16_rn(v.y - __bfloat162float(h1));
            __nv_bfloat16 l2 = __float2bfloat16_rn(v.z - __bfloat162float(h2));
            __nv_bfloat16 l3 = __float2bfloat16_rn(v.w - __bfloat162float(h3));
            __nv_bfloat162 hp0 = {h0, h1}, hp1 = {h2, h3};
            __nv_bfloat162 lp0 = {l0, l1}, lp1 = {l2, l3};
            int off = r * A_STRIDE + 4 * c4;
            *(uint2*)&Ahi[off] = make_uint2(*(uint32_t*)&hp0, *(uint32_t*)&hp1);
            *(uint2*)&Alo[off] = make_uint2(*(uint32_t*)&lp0, *(uint32_t*)&lp1);
        }
    };
    auto do_mma = [&](int c) {
        const uint32_t ahi_base = sbase + BF_OFF;
        const uint32_t alo_base = ahi_base + AHALF;
        const uint32_t* __restrict__ bhp = (const uint32_t*)(g_Bhi + c * 8192);
        const uint32_t* __restrict__ blp = (const uint32_t*)(g_Blo + c * 8192);
        const int bq = lane & 3;
#pragma unroll
        for (int ks = 0; ks < 4; ks++) {
            const int k0 = ks * 16;
            uint32_t ah[2][4], al[2][4];
#pragma unroll
            for (int mt = 0; mt < 2; mt++) {
                int m = warp_m * 32 + mt * 16 + lm_row;
                uint32_t byteoff = (uint32_t)(m * (A_STRIDE * 2) + k0 * 2 + lm_koff);
                ldmatrix_x4(ah[mt][0], ah[mt][1], ah[mt][2], ah[mt][3],
                            ahi_base + byteoff);
                ldmatrix_x4(al[mt][0], al[mt][1], al[mt][2], al[mt][3],
                            alo_base + byteoff);
            }
            uint32_t bh[4][2], bl[4][2];
#pragma unroll
            for (int nt = 0; nt < 4; nt++) {
                int n = warp_n * 32 + nt * 8 + (lane >> 2);
                int base = n * 32 + (k0 >> 1) + bq;
                bh[nt][0] = bhp[base];
                bh[nt][1] = bhp[base + 4];
                bl[nt][0] = blp[base];
                bl[nt][1] = blp[base + 4];
            }
#pragma unroll
            for (int mt = 0; mt < 2; mt++)
#pragma unroll
                for (int nt = 0; nt < 4; nt++) {
                    float* d = acc[mt][nt];
                    mma_bf16(d[0], d[1], d[2], d[3],
                             ah[mt][0], ah[mt][1], ah[mt][2], ah[mt][3],
                             bh[nt][0], bh[nt][1]);
                    mma_bf16(d[0], d[1], d[2], d[3],
                             ah[mt][0], ah[mt][1], ah[mt][2], ah[mt][3],
                             bl[nt][0], bl[nt][1]);
                    mma_bf16(d[0], d[1], d[2], d[3],
                             al[mt][0], al[mt][1], al[mt][2], al[mt][3],
                             bh[nt][0], bh[nt][1]);
                }
        }
    };

    // ---- pipelined mainloop ----
    issue_cp(0, 0);
    cp_wait0();                  // own bytes arrived (thread converts what it copied)
    convert(0);
    __syncthreads();
#pragma unroll
    for (int c = 0; c < 4; c++) {
        if (c < 3) issue_cp(c + 1, (c + 1) & 1);   // DRAM copy rides under MMA
        do_mma(c);
        __syncthreads();                            // all warps done reading bf16
        if (c < 3) {
            cp_wait0();
            convert((c + 1) & 1);
            __syncthreads();
        }
    }

    // ---- epilogue: add bias to cols<64, store float2 pairs ----
    const int crow = lane >> 2;
    const int ccol = (lane & 3) * 2;
#pragma unroll
    for (int nt = 0; nt < 4; nt++) {
        int col = warp_n * 32 + nt * 8 + ccol;
        float2 bv = make_float2(0.f, 0.f);
        if (col < 64) bv = *(const float2*)&b1[col];
#pragma unroll
        for (int mt = 0; mt < 2; mt++) {
            int m = warp_m * 32 + mt * 16 + crow;
            int grow0 = row0 + m;
            int grow1 = grow0 + 8;
            float* d = acc[mt][nt];
            if (grow0 < N_NODES)
                *(float2*)&g_T[(size_t)grow0 * 128 + col] =
                    make_float2(d[0] + bv.x, d[1] + bv.y);
            if (grow1 < N_NODES)
                *(float2*)&g_T[(size_t)grow1 * 128 + col] =
                    make_float2(d[2] + bv.x, d[3] + bv.y);
        }
    }
}

// ============================================================================
// Kernel 2: gather + head. Half-warp per sample; lane l -> float4 of hidden.
// ============================================================================
__global__ __launch_bounds__(256)
void gather_kernel(const void* __restrict__ ts_raw,
                   const float* __restrict__ w2,
                   float* __restrict__ out, int n)
{
    int hs   = (blockIdx.x * blockDim.x + threadIdx.x) >> 4;
    int lane = threadIdx.x & 15;
    if (hs >= n) return;

    long long src, dst;
    if (g_idx_is64) {
        longlong2 sd = ((const longlong2*)ts_raw)[hs];
        src = sd.x; dst = sd.y;
    } else {
        int2 sd = ((const int2*)ts_raw)[hs];
        src = sd.x; dst = sd.y;
    }
    src = min(max(src, 0LL), (long long)(N_NODES - 1));
    dst = min(max(dst, 0LL), (long long)(N_NODES - 1));

    float4 s = *(const float4*)(g_T + (size_t)src * 128 + 4 * lane);
    float4 d = *(const float4*)(g_T + (size_t)dst * 128 + 64 + 4 * lane);
    float4 w = ((const float4*)w2)[lane];

    float p = fmaxf(s.x + d.x, 0.f) * w.x
            + fmaxf(s.y + d.y, 0.f) * w.y
            + fmaxf(s.z + d.z, 0.f) * w.z
            + fmaxf(s.w + d.w, 0.f) * w.w;

#pragma unroll
    for (int off = 8; off; off >>= 1)
        p += __shfl_xor_sync(0xffffffffu, p, off);

    if (lane == 0) out[hs] = p;
}

// ============================================================================
extern "C" void kernel_launch(void* const* d_in, const int* in_sizes, int n_in,
                              void* d_out, int out_size)
{
    const float* in1 = (const float*)d_in[0];      // (100000,128) f32
    const float* in2 = (const float*)d_in[1];      // (100000,128) f32
    const void*  ts  = d_in[2];                    // (250000,2) int32/int64
    const float* w1  = (const float*)d_in[3];      // (512,64) f32
    const float* b1  = (const float*)d_in[4];      // (64,)   f32
    const float* w2  = (const float*)d_in[5];      // (64,1)  f32
    float*       out = (float*)d_out;              // (250000,1) f32

    (void)in_sizes; (void)n_in; (void)out_size;

    prep_kernel<<<32, 256>>>((const unsigned int*)ts, w1);

    cudaFuncSetAttribute(precompute_mma_kernel,
                         cudaFuncAttributeMaxDynamicSharedMemorySize, SMEM_TOT);
    precompute_mma_kernel<<<(N_NODES + 127) / 128, 512, SMEM_TOT>>>(in1, in2, b1);

    int samples_per_block = 256 / 16;   // 16 samples per 256-thread block
    int blocks = (N_SAMPLES + samples_per_block - 1) / samples_per_block;
    gather_kernel<<<blocks, 256>>>(ts, w2, out, N_SAMPLES);
}

// round 8
// speedup vs baseline: 1.0659x; 1.0659x over previous
#include <cuda_runtime.h>
#include <cuda_bf16.h>
#include <cstdint>

#define N_NODES   100000
#define D_FEAT    128
#define HID       64
#define N_SAMPLES 250000

// Merged per-node table (51.2 MB scratch).
// T[n][ 0: 64] = x1[n]@w1[0:128]   + x2[n]@w1[256:384] + b1   (src half)
// T[n][64:128] = x1[n]@w1[128:256] + x2[n]@w1[384:512]        (dst half)
__device__ float g_T[(size_t)N_NODES * 128];

// Pre-split B operand, chunk-major: [chunk c][n 0..127][kk 0..63] bf16.
__device__ __nv_bfloat16 g_Bhi[4 * 128 * 64];
__device__ __nv_bfloat16 g_Blo[4 * 128 * 64];

__device__ int g_idx_is64;   // 1 if train_sample is int64, 0 if int32

// ---------------- helpers ----------------
__device__ __forceinline__ uint32_t smem_u32(const void* p) {
    uint32_t a;
    asm("{ .reg .u64 t; cvta.to.shared.u64 t, %1; cvt.u32.u64 %0, t; }"
        : "=r"(a) : "l"(p));
    return a;
}
__device__ __forceinline__ void ldmatrix_x4(uint32_t& r0, uint32_t& r1,
                                            uint32_t& r2, uint32_t& r3,
                                            uint32_t addr) {
    asm volatile("ldmatrix.sync.aligned.m8n8.x4.shared.b16 {%0,%1,%2,%3}, [%4];"
                 : "=r"(r0), "=r"(r1), "=r"(r2), "=r"(r3) : "r"(addr));
}
__device__ __forceinline__ void mma_bf16(float& d0, float& d1, float& d2, float& d3,
                                         uint32_t a0, uint32_t a1, uint32_t a2, uint32_t a3,
                                         uint32_t b0, uint32_t b1) {
    asm volatile(
        "mma.sync.aligned.m16n8k16.row.col.f32.bf16.bf16.f32 "
        "{%0,%1,%2,%3}, {%4,%5,%6,%7}, {%8,%9}, {%0,%1,%2,%3};"
        : "+f"(d0), "+f"(d1), "+f"(d2), "+f"(d3)
        : "r"(a0), "r"(a1), "r"(a2), "r"(a3), "r"(b0), "r"(b1));
}

// ============================================================================
// Kernel 0: dtype detect (block 0) + B split (128 blocks, 1 elem/thread).
// B[c][n][kk] = w1[wrow][wcol], gk = 64c + kk:
//   n<64 : wrow = gk<128 ? gk     : gk+128 ; wcol = n
//   n>=64: wrow = gk<128 ? gk+128 : gk+256 ; wcol = n-64
// ============================================================================
__global__ void prep_kernel(const unsigned int* __restrict__ ts32,
                            const float* __restrict__ w1)
{
    int t = threadIdx.x;

    if (blockIdx.x == 0) {
        __shared__ int nonzero;
        if (t == 0) nonzero = 0;
        __syncthreads();
        unsigned int acc = 0;
#pragma unroll
        for (int i = 0; i < 16; i++) acc |= ts32[2 * (t + 256 * i) + 1];
        if (acc) atomicOr(&nonzero, 1);
        __syncthreads();
        if (t == 0) g_idx_is64 = nonzero ? 0 : 1;
    }

    int idx = blockIdx.x * 256 + t;                // 0..32767
    int c  = idx >> 13;
    int n  = (idx >> 6) & 127;
    int kk = idx & 63;
    int gk = c * 64 + kk;
    int wrow = (n < 64) ? ((gk < 128) ? gk : gk + 128)
                        : ((gk < 128) ? gk + 128 : gk + 256);
    int wcol = n & 63;
    float v = w1[wrow * HID + wcol];
    __nv_bfloat16 h = __float2bfloat16_rn(v);
    __nv_bfloat16 l = __float2bfloat16_rn(v - __bfloat162float(h));
    g_Bhi[idx] = h;
    g_Blo[idx] = l;
}

// ============================================================================
// Kernel 1: warp-MMA precompute GEMM (bf16 hi/lo split, fp32 accumulate).
// CTA: 256 threads (8 warps), 64M x 128N, K=256 in four 64-chunks.
// Warp tile 32x32 (2x4 m16n8 tiles), acc=32 regs -> ~100 regs total, 18.4 KB
// smem -> 2 CTAs/SM: co-resident CTA's MMA phase hides this CTA's load phase.
// Serial phases inside the CTA (proven-best R5 structure).
// B frags direct from pre-split global scratch (L1-resident).
// ============================================================================
#define A_STRIDE 72   // bf16 elems per smem row (64 data + 8 pad), 144 B

__global__ __launch_bounds__(256, 2)
void precompute_mma_kernel(const float* __restrict__ in1,
                           const float* __restrict__ in2,
                           const float* __restrict__ b1)
{
    __shared__ __nv_bfloat16 Ahi[64 * A_STRIDE];
    __shared__ __nv_bfloat16 Alo[64 * A_STRIDE];

    const int t      = threadIdx.x;
    const int wid    = t >> 5;
    const int lane   = t & 31;
    const int warp_m = wid >> 2;         // 0..1  (32-row strips)
    const int warp_n = wid & 3;          // 0..3  (32-col strips)
    const int row0   = blockIdx.x * 64;

    const uint32_t ahi_base = smem_u32(Ahi);
    const uint32_t alo_base = smem_u32(Alo);

    float acc[2][4][4];
#pragma unroll
    for (int mt = 0; mt < 2; mt++)
#pragma unroll
        for (int nt = 0; nt < 4; nt++)
#pragma unroll
            for (int r = 0; r < 4; r++) acc[mt][nt][r] = 0.f;

    const int lm_row  = lane & 15;
    const int lm_koff = (lane >> 4) * 16;

    for (int c = 0; c < 4; c++) {
        if (c) __syncthreads();               // protect smem reuse

        // ---- stage A chunk: 64 rows x 64 k fp32, split hi/lo, store bf16 ----
        const float* __restrict__ in = (c < 2) ? in1 : in2;
        const int col0 = (c & 1) * 64;
#pragma unroll
        for (int i = 0; i < 4; i++) {
            int linear = t + 256 * i;          // 0..1023 float4 slots
            int r  = linear >> 4;              // row 0..63
            int c4 = linear & 15;              // float4 slot along k
            int grow = row0 + r;
            float4 v = make_float4(0.f, 0.f, 0.f, 0.f);
            if (grow < N_NODES)
                v = *(const float4*)&in[(size_t)grow * D_FEAT + col0 + 4 * c4];
            __nv_bfloat16 h0 = __float2bfloat16_rn(v.x), h1 = __float2bfloat16_rn(v.y);
            __nv_bfloat16 h2 = __float2bfloat16_rn(v.z), h3 = __float2bfloat16_rn(v.w);
            __nv_bfloat16 l0 = __float2bfloat16_rn(v.x - __bfloat162float(h0));
            __nv_bfloat16 l1 = __float2bfloat16_rn(v.y - __bfloat162float(h1));
            __nv_bfloat16 l2 = __float2bfloat16_rn(v.z - __bfloat162float(h2));
            __nv_bfloat16 l3 = __float2bfloat16_rn(v.w - __bfloat162float(h3));
            __nv_bfloat162 hp0 = {h0, h1}, hp1 = {h2, h3};
            __nv_bfloat162 lp0 = {l0, l1}, lp1 = {l2, l3};
            int off = r * A_STRIDE + 4 * c4;
            *(uint2*)&Ahi[off] = make_uint2(*(uint32_t*)&hp0, *(uint32_t*)&hp1);
            *(uint2*)&Alo[off] = make_uint2(*(uint32_t*)&lp0, *(uint32_t*)&lp1);
        }
        __syncthreads();

        // ---- B fragment base pointers for this chunk ----
        const uint32_t* __restrict__ bhp = (const uint32_t*)(g_Bhi + c * 8192);
        const uint32_t* __restrict__ blp = (const uint32_t*)(g_Blo + c * 8192);
        const int bq = lane & 3;

#pragma unroll
        for (int ks = 0; ks < 4; ks++) {
            const int k0 = ks * 16;

            uint32_t ah[2][4], al[2][4];
#pragma unroll
            for (int mt = 0; mt < 2; mt++) {
                int m = warp_m * 32 + mt * 16 + lm_row;
                uint32_t byteoff = (uint32_t)(m * (A_STRIDE * 2) + k0 * 2 + lm_koff);
                ldmatrix_x4(ah[mt][0], ah[mt][1], ah[mt][2], ah[mt][3],
                            ahi_base + byteoff);
                ldmatrix_x4(al[mt][0], al[mt][1], al[mt][2], al[mt][3],
                            alo_base + byteoff);
            }
            uint32_t bh[4][2], bl[4][2];
#pragma unroll
            for (int nt = 0; nt < 4; nt++) {
                int n = warp_n * 32 + nt * 8 + (lane >> 2);
                int base = n * 32 + (k0 >> 1) + bq;
                bh[nt][0] = bhp[base];
                bh[nt][1] = bhp[base + 4];
                bl[nt][0] = blp[base];
                bl[nt][1] = blp[base + 4];
            }
#pragma unroll
            for (int mt = 0; mt < 2; mt++)
#pragma unroll
                for (int nt = 0; nt < 4; nt++) {
                    float* d = acc[mt][nt];
                    mma_bf16(d[0], d[1], d[2], d[3],
                             ah[mt][0], ah[mt][1], ah[mt][2], ah[mt][3],
                             bh[nt][0], bh[nt][1]);
                    mma_bf16(d[0], d[1], d[2], d[3],
                             ah[mt][0], ah[mt][1], ah[mt][2], ah[mt][3],
                             bl[nt][0], bl[nt][1]);
                    mma_bf16(d[0], d[1], d[2], d[3],
                             al[mt][0], al[mt][1], al[mt][2], al[mt][3],
                             bh[nt][0], bh[nt][1]);
                }
        }
    }

    // ---- epilogue: add bias to cols<64, store float2 pairs ----
    const int crow = lane >> 2;
    const int ccol = (lane & 3) * 2;
#pragma unroll
    for (int nt = 0; nt < 4; nt++) {
        int col = warp_n * 32 + nt * 8 + ccol;
        float2 bv = make_float2(0.f, 0.f);
        if (col < 64) bv = *(const float2*)&b1[col];
#pragma unroll
        for (int mt = 0; mt < 2; mt++) {
            int m = warp_m * 32 + mt * 16 + crow;
            int grow0 = row0 + m;
            int grow1 = grow0 + 8;
            float* d = acc[mt][nt];
            if (grow0 < N_NODES)
                *(float2*)&g_T[(size_t)grow0 * 128 + col] =
                    make_float2(d[0] + bv.x, d[1] + bv.y);
            if (grow1 < N_NODES)
                *(float2*)&g_T[(size_t)grow1 * 128 + col] =
                    make_float2(d[2] + bv.x, d[3] + bv.y);
        }
    }
}

// ============================================================================
// Kernel 2: gather + head. Half-warp per sample; lane l -> float4 of hidden.
// ============================================================================
__global__ __launch_bounds__(256)
void gather_kernel(const void* __restrict__ ts_raw,
                   const float* __restrict__ w2,
                   float* __restrict__ out, int n)
{
    int hs   = (blockIdx.x * blockDim.x + threadIdx.x) >> 4;
    int lane = threadIdx.x & 15;
    if (hs >= n) return;

    long long src, dst;
    if (g_idx_is64) {
        longlong2 sd = ((const longlong2*)ts_raw)[hs];
        src = sd.x; dst = sd.y;
    } else {
        int2 sd = ((const int2*)ts_raw)[hs];
        src = sd.x; dst = sd.y;
    }
    src = min(max(src, 0LL), (long long)(N_NODES - 1));
    dst = min(max(dst, 0LL), (long long)(N_NODES - 1));

    float4 s = *(const float4*)(g_T + (size_t)src * 128 + 4 * lane);
    float4 d = *(const float4*)(g_T + (size_t)dst * 128 + 64 + 4 * lane);
    float4 w = ((const float4*)w2)[lane];

    float p = fmaxf(s.x + d.x, 0.f) * w.x
            + fmaxf(s.y + d.y, 0.f) * w.y
            + fmaxf(s.z + d.z, 0.f) * w.z
            + fmaxf(s.w + d.w, 0.f) * w.w;

#pragma unroll
    for (int off = 8; off; off >>= 1)
        p += __shfl_xor_sync(0xffffffffu, p, off);

    if (lane == 0) out[hs] = p;
}

// ============================================================================
extern "C" void kernel_launch(void* const* d_in, const int* in_sizes, int n_in,
                              void* d_out, int out_size)
{
    const float* in1 = (const float*)d_in[0];      // (100000,128) f32
    const float* in2 = (const float*)d_in[1];      // (100000,128) f32
    const void*  ts  = d_in[2];                    // (250000,2) int32/int64
    const float* w1  = (const float*)d_in[3];      // (512,64) f32
    const float* b1  = (const float*)d_in[4];      // (64,)   f32
    const float* w2  = (const float*)d_in[5];      // (64,1)  f32
    float*       out = (float*)d_out;              // (250000,1) f32

    (void)in_sizes; (void)n_in; (void)out_size;

    prep_kernel<<<128, 256>>>((const unsigned int*)ts, w1);

    precompute_mma_kernel<<<(N_NODES + 63) / 64, 256>>>(in1, in2, b1);

    int samples_per_block = 256 / 16;   // 16 samples per 256-thread block
    int blocks = (N_SAMPLES + samples_per_block - 1) / samples_per_block;
    gather_kernel<<<blocks, 256>>>(ts, w2, out, N_SAMPLES);
}